// round 16
// baseline (speedup 1.0000x reference)
#include <cuda_runtime.h>
#include <cuda_fp16.h>
#include <cstdint>

#define N_NODES 50000
#define N_EDGES 800000
#define IN_SIZE 1024
#define EMB 500
#define EMBP 512
#define CLW 1024    // combined conv|lin output width
#define M_TOP 25088 // 196 * 128
#define M_BOT (N_NODES - M_TOP)   // 24912

// ---------------------------------------------------------------------------
// Scratch (device globals: allocation-free per harness rules)
// ---------------------------------------------------------------------------
__device__ __half g_xh[(size_t)N_NODES * IN_SIZE];     // x -> fp16
__device__ __half g_h[(size_t)N_NODES * EMBP];         // sigmoid(enc) fp16
__device__ __half g_hw[(size_t)N_NODES * CLW];         // [h2 | agg_lin] fp16
__device__ __half g_aggh[(size_t)N_NODES * EMBP];      // final agg fp16
// fp16 weights, padded [NP][Kp], K contiguous
__device__ __half g_wench[EMBP * IN_SIZE];
__device__ __half g_clh[CLW * EMBP];                   // [conv^T ; lin] stacked
__device__ __half g_wdech[IN_SIZE * EMBP];
// CSR scratch
__device__ int   g_cnt[N_NODES + 1];
__device__ int   g_cur[N_NODES];
__device__ int   g_esrc[N_EDGES];
__device__ float g_ewt[N_EDGES];

// ---------------------------------------------------------------------------
// Convert kernels
// ---------------------------------------------------------------------------
__global__ __launch_bounds__(256) void convert_x_kernel(
    const float4* __restrict__ x, __half* __restrict__ xh, long long n4)
{
    long long i = (long long)blockIdx.x * blockDim.x + threadIdx.x;
    if (i >= n4) return;
    float4 v = x[i];
    __half2* p = reinterpret_cast<__half2*>(xh) + i * 2;
    p[0] = __floats2half2_rn(v.x, v.y);
    p[1] = __floats2half2_rn(v.z, v.w);
}

template <bool TRANS>
__global__ __launch_bounds__(256) void convert_w_kernel(
    const float* __restrict__ src, __half* __restrict__ dst,
    int N, int K, int NP, int Kp)
{
    int idx = blockIdx.x * blockDim.x + threadIdx.x;
    if (idx >= NP * Kp) return;
    int n = idx / Kp, k = idx - n * Kp;
    float v = 0.f;
    if (n < N && k < K)
        v = TRANS ? src[(long long)k * N + n] : src[(long long)n * K + k];
    dst[idx] = __float2half_rn(v);
}

// ---------------------------------------------------------------------------
// CSR build kernels
// ---------------------------------------------------------------------------
__global__ __launch_bounds__(256) void k_zero_cnt()
{
    int i = blockIdx.x * blockDim.x + threadIdx.x;
    if (i <= N_NODES) g_cnt[i] = 0;
}
__global__ __launch_bounds__(256) void k_count(const int* __restrict__ edge_index)
{
    int e = blockIdx.x * blockDim.x + threadIdx.x;
    if (e < N_EDGES) atomicAdd(&g_cnt[edge_index[N_EDGES + e]], 1);
}
#define SCAN_T 1024
#define SCAN_C 49   // 1024*49 = 50176 >= 50000
__global__ __launch_bounds__(SCAN_T) void k_scan()
{
    __shared__ int sh[SCAN_T];
    const int t = threadIdx.x;
    const int base = t * SCAN_C;
    int s = 0;
    #pragma unroll 4
    for (int j = 0; j < SCAN_C; j++) {
        int idx = base + j;
        if (idx < N_NODES) s += g_cnt[idx];
    }
    sh[t] = s;
    __syncthreads();
    for (int off = 1; off < SCAN_T; off <<= 1) {
        int v = (t >= off) ? sh[t - off] : 0;
        __syncthreads();
        sh[t] += v;
        __syncthreads();
    }
    int run = sh[t] - s;  // exclusive prefix
    for (int j = 0; j < SCAN_C; j++) {
        int idx = base + j;
        if (idx < N_NODES) {
            int c = g_cnt[idx];
            g_cnt[idx] = run;
            g_cur[idx] = run;
            run += c;
        }
    }
    if (t == 0) g_cnt[N_NODES] = N_EDGES;
}
__global__ __launch_bounds__(256) void k_fill(
    const int* __restrict__ edge_index, const float* __restrict__ ew)
{
    int e = blockIdx.x * blockDim.x + threadIdx.x;
    if (e >= N_EDGES) return;
    int dst = edge_index[N_EDGES + e];
    int pos = atomicAdd(&g_cur[dst], 1);
    g_esrc[pos] = edge_index[e];
    g_ewt[pos]  = ew[e];
}

// ---------------------------------------------------------------------------
// Gather (no atomics): acc = lin_part[n] + sum_e w_e * h2_part[src_e].
// hw row n = [h2 (512 fp16) | agg_lin (512 fp16)].
// 2 nodes per 128-thread block; each thread owns one 16B chunk (8 halves).
// ---------------------------------------------------------------------------
__global__ __launch_bounds__(128) void gather_nodes(
    const __half* __restrict__ hw, __half* __restrict__ aggh)
{
    const int n = blockIdx.x * 2 + (threadIdx.x >> 6);
    const int t = threadIdx.x & 63;        // 16B chunk within the 512-half row
    const int c = t * 8;                   // half index 0..504
    const int beg = g_cnt[n], end = g_cnt[n + 1];

    float acc[8];
    {   // base = lin part (cols 512..1023)
        uint4 bv = *reinterpret_cast<const uint4*>(hw + (long long)n * CLW + EMBP + c);
        const __half2* hb = reinterpret_cast<const __half2*>(&bv);
        #pragma unroll
        for (int j = 0; j < 4; j++) {
            float2 f = __half22float2(hb[j]);
            acc[j * 2] = f.x; acc[j * 2 + 1] = f.y;
        }
    }

    int e = beg;
    for (; e + 3 < end; e += 4) {
        int   s0 = g_esrc[e],   s1 = g_esrc[e+1], s2 = g_esrc[e+2], s3 = g_esrc[e+3];
        float w0 = g_ewt[e],    w1 = g_ewt[e+1],  w2 = g_ewt[e+2],  w3 = g_ewt[e+3];
        uint4 v0 = *reinterpret_cast<const uint4*>(hw + (long long)s0 * CLW + c);
        uint4 v1 = *reinterpret_cast<const uint4*>(hw + (long long)s1 * CLW + c);
        uint4 v2 = *reinterpret_cast<const uint4*>(hw + (long long)s2 * CLW + c);
        uint4 v3 = *reinterpret_cast<const uint4*>(hw + (long long)s3 * CLW + c);
        const __half2* h0 = reinterpret_cast<const __half2*>(&v0);
        const __half2* h1 = reinterpret_cast<const __half2*>(&v1);
        const __half2* h2 = reinterpret_cast<const __half2*>(&v2);
        const __half2* h3 = reinterpret_cast<const __half2*>(&v3);
        #pragma unroll
        for (int j = 0; j < 4; j++) {
            float2 f;
            f = __half22float2(h0[j]);
            acc[j*2] = fmaf(f.x, w0, acc[j*2]); acc[j*2+1] = fmaf(f.y, w0, acc[j*2+1]);
            f = __half22float2(h1[j]);
            acc[j*2] = fmaf(f.x, w1, acc[j*2]); acc[j*2+1] = fmaf(f.y, w1, acc[j*2+1]);
            f = __half22float2(h2[j]);
            acc[j*2] = fmaf(f.x, w2, acc[j*2]); acc[j*2+1] = fmaf(f.y, w2, acc[j*2+1]);
            f = __half22float2(h3[j]);
            acc[j*2] = fmaf(f.x, w3, acc[j*2]); acc[j*2+1] = fmaf(f.y, w3, acc[j*2+1]);
        }
    }
    for (; e < end; e++) {
        int   s0 = g_esrc[e];
        float w0 = g_ewt[e];
        uint4 v0 = *reinterpret_cast<const uint4*>(hw + (long long)s0 * CLW + c);
        const __half2* h0 = reinterpret_cast<const __half2*>(&v0);
        #pragma unroll
        for (int j = 0; j < 4; j++) {
            float2 f = __half22float2(h0[j]);
            acc[j*2] = fmaf(f.x, w0, acc[j*2]); acc[j*2+1] = fmaf(f.y, w0, acc[j*2+1]);
        }
    }

    uint4 ov;
    __half2* oh = reinterpret_cast<__half2*>(&ov);
    #pragma unroll
    for (int j = 0; j < 4; j++)
        oh[j] = __floats2half2_rn(acc[j * 2], acc[j * 2 + 1]);
    *reinterpret_cast<uint4*>(aggh + (long long)n * EMBP + c) = ov;
}

// ---------------------------------------------------------------------------
// Single-term fp16 GEMM, mma.sync m16n8k16 + cp.async 4-stage pipeline.
// C[M,N] = act(A[M,K] @ B[N,K]^T + bias). BM=BN=128, BK=32, 256 thr, 2 CTA/SM.
// smem rows padded to 40 halves (80B stride; conflict-free ldmatrix).
// OMODE: 0 = fp32 out, 2 = fp16 out. K mult of 32 (nk >= 16), B rows padded.
// ---------------------------------------------------------------------------
#define KPAD 40
#define TILE_BYTES (128 * KPAD * 2)        // 10240 per matrix
#define STAGE_BYTES (2 * TILE_BYTES)       // 20480
#define NSTAGE 4
#define DYNSMEM (NSTAGE * STAGE_BYTES)     // 81920 -> 2 CTAs/SM

__device__ __forceinline__ void ldsm4(uint32_t (&r)[4], uint32_t addr) {
    asm volatile("ldmatrix.sync.aligned.m8n8.x4.shared.b16 {%0,%1,%2,%3}, [%4];"
                 : "=r"(r[0]), "=r"(r[1]), "=r"(r[2]), "=r"(r[3]) : "r"(addr));
}
__device__ __forceinline__ void mma_f16(float (&c)[4], const uint32_t (&a)[4],
                                        uint32_t b0, uint32_t b1) {
    asm volatile(
        "mma.sync.aligned.m16n8k16.row.col.f32.f16.f16.f32 "
        "{%0,%1,%2,%3}, {%4,%5,%6,%7}, {%8,%9}, {%0,%1,%2,%3};"
        : "+f"(c[0]), "+f"(c[1]), "+f"(c[2]), "+f"(c[3])
        : "r"(a[0]), "r"(a[1]), "r"(a[2]), "r"(a[3]), "r"(b0), "r"(b1));
}
__device__ __forceinline__ void cpa16(uint32_t dst, const void* src, int sz) {
    asm volatile("cp.async.cg.shared.global [%0], [%1], 16, %2;"
                 :: "r"(dst), "l"(src), "r"(sz) : "memory");
}
__device__ __forceinline__ void cpa16u(uint32_t dst, const void* src) {
    asm volatile("cp.async.cg.shared.global [%0], [%1], 16;"
                 :: "r"(dst), "l"(src) : "memory");
}

template <int OMODE, bool BIAS, bool SIG>
__global__ __launch_bounds__(256, 2) void hgemm(
    const __half* __restrict__ A, int sA_,
    const __half* __restrict__ B, int sB_,
    const float* __restrict__ bias,
    float* __restrict__ C, __half* __restrict__ Ch, int sC,
    int M, int Nreal, int K)
{
    extern __shared__ char smem[];

    const int tid  = threadIdx.x;
    const int lane = tid & 31;
    const int warp = tid >> 5;
    const int wm = warp >> 1;   // 0..3
    const int wn = warp & 1;    // 0..1
    const int m0 = blockIdx.y * 128;
    const int n0 = blockIdx.x * 128;

    const int lrow = tid >> 1;
    const int cp0  = (tid & 1) * 2;
    const int gmA  = m0 + lrow;
    const int szA  = (gmA < M) ? 16 : 0;
    const __half* srcA = A + (long long)gmA * sA_ + cp0 * 8;
    const __half* srcB = B + (long long)(n0 + lrow) * sB_ + cp0 * 8;
    const uint32_t smem_u = (uint32_t)__cvta_generic_to_shared(smem);
    const uint32_t dRow = (uint32_t)(lrow * (KPAD * 2) + cp0 * 16);

    float acc[2][8][4];
    #pragma unroll
    for (int i = 0; i < 2; i++)
        #pragma unroll
        for (int j = 0; j < 8; j++)
            #pragma unroll
            for (int e = 0; e < 4; e++) acc[i][j][e] = 0.f;

    const int g = lane >> 3, r8 = lane & 7;
    const int nk = K / 32;

    auto load_stage = [&](int st, int k0) {
        const uint32_t aBase = smem_u + st * STAGE_BYTES + dRow;
        const uint32_t bBase = aBase + TILE_BYTES;
        cpa16(aBase,      srcA + k0, szA);
        cpa16(aBase + 16, srcA + k0 + 8, szA);
        cpa16u(bBase,      srcB + k0);
        cpa16u(bBase + 16, srcB + k0 + 8);
        asm volatile("cp.async.commit_group;" ::: "memory");
    };

    // prologue: 3 stages in flight (nk >= 16 always)
    load_stage(0, 0);
    load_stage(1, 32);
    load_stage(2, 64);

    const int aRowBase = wm * 32 + (g & 1) * 8 + r8;
    const int aColB    = (g >> 1) * 16;
    const int bRowBase = wn * 64 + (g >> 1) * 8 + r8;
    const int bColB    = (g & 1) * 16;

    for (int s = 0; s < nk; s++) {
        const int rem = nk - 1 - s;
        if (rem >= 2)      { asm volatile("cp.async.wait_group 2;" ::: "memory"); }
        else if (rem == 1) { asm volatile("cp.async.wait_group 1;" ::: "memory"); }
        else               { asm volatile("cp.async.wait_group 0;" ::: "memory"); }
        __syncthreads();   // stage s visible; all warps done with stage s-1 reads
        if (s + 3 < nk) load_stage((s + 3) % NSTAGE, (s + 3) * 32);

        const uint32_t aBuf = smem_u + (s % NSTAGE) * STAGE_BYTES;
        const uint32_t bBuf = aBuf + TILE_BYTES;

        #pragma unroll
        for (int ks = 0; ks < 2; ks++) {
            const int kkB = ks * 32;
            uint32_t a[2][4];
            #pragma unroll
            for (int mt = 0; mt < 2; mt++)
                ldsm4(a[mt], aBuf + (uint32_t)((aRowBase + mt * 16) * (KPAD * 2)
                                               + kkB + aColB));
            #pragma unroll
            for (int p = 0; p < 4; p++) {
                uint32_t b[4];
                ldsm4(b, bBuf + (uint32_t)((bRowBase + p * 16) * (KPAD * 2)
                                           + kkB + bColB));
                #pragma unroll
                for (int sx = 0; sx < 2; sx++)
                    #pragma unroll
                    for (int mt = 0; mt < 2; mt++)
                        mma_f16(acc[mt][p * 2 + sx], a[mt],
                                b[sx * 2], b[sx * 2 + 1]);
            }
        }
    }

    // ---- epilogue: packed stores (e-pairs are adjacent columns) ----
    const int rq = lane >> 2, cq = (lane & 3) * 2;
    #pragma unroll
    for (int mt = 0; mt < 2; mt++)
        #pragma unroll
        for (int nt = 0; nt < 8; nt++) {
            const int gc = n0 + wn * 64 + nt * 8 + cq;   // even
            #pragma unroll
            for (int half_ : {0, 1}) {
                const int gm = m0 + wm * 32 + mt * 16 + rq + half_ * 8;
                if (gm >= M) continue;
                float v0 = acc[mt][nt][half_ * 2 + 0];
                float v1 = acc[mt][nt][half_ * 2 + 1];
                if (BIAS || SIG) {
                    if (gc < Nreal)     { if (BIAS) v0 += bias[gc]; }
                    else v0 = 0.f;
                    if (gc + 1 < Nreal) { if (BIAS) v1 += bias[gc + 1]; }
                    else v1 = 0.f;
                    if (SIG) {
                        if (gc < Nreal)     v0 = 1.f / (1.f + expf(-v0));
                        if (gc + 1 < Nreal) v1 = 1.f / (1.f + expf(-v1));
                    }
                }
                if (OMODE == 2) {
                    *reinterpret_cast<__half2*>(Ch + (long long)gm * sC + gc)
                        = __floats2half2_rn(v0, v1);
                } else {
                    *reinterpret_cast<float2*>(C + (long long)gm * sC + gc)
                        = make_float2(v0, v1);
                }
            }
        }
}

// ---------------------------------------------------------------------------
extern "C" void kernel_launch(void* const* d_in, const int* in_sizes, int n_in,
                              void* d_out, int out_size)
{
    const float* x           = (const float*)d_in[0];
    const int*   edge_index  = (const int*)  d_in[1];
    const float* edge_weight = (const float*)d_in[2];
    const float* wenc        = (const float*)d_in[3];  // [EMB, IN_SIZE]
    const float* benc        = (const float*)d_in[4];
    const float* wdec        = (const float*)d_in[5];  // [IN_SIZE, EMB]
    const float* bdec        = (const float*)d_in[6];
    const float* conv_weight = (const float*)d_in[7];  // [EMB, EMB] (k, n)
    const float* lin_weight  = (const float*)d_in[8];  // [EMB, EMB] (n, k)
    float* out = (float*)d_out;

    __half *xh, *h, *hw, *aggh, *wench, *clh, *wdech;
    cudaGetSymbolAddress((void**)&xh, g_xh);
    cudaGetSymbolAddress((void**)&h, g_h);
    cudaGetSymbolAddress((void**)&hw, g_hw);
    cudaGetSymbolAddress((void**)&aggh, g_aggh);
    cudaGetSymbolAddress((void**)&wench, g_wench);
    cudaGetSymbolAddress((void**)&clh, g_clh);
    cudaGetSymbolAddress((void**)&wdech, g_wdech);

    cudaFuncSetAttribute(hgemm<2, true,  true >, cudaFuncAttributeMaxDynamicSharedMemorySize, DYNSMEM);
    cudaFuncSetAttribute(hgemm<2, false, false>, cudaFuncAttributeMaxDynamicSharedMemorySize, DYNSMEM);
    cudaFuncSetAttribute(hgemm<0, true,  false>, cudaFuncAttributeMaxDynamicSharedMemorySize, DYNSMEM);

    const int mt  = (N_NODES + 127) / 128;    // 391
    const int mtT = M_TOP / 128;              // 196
    const int mtB = (M_BOT + 127) / 128;      // 195

    // ---- ONE side stream + 5 events (same graph scale that passed in R14;
    // created per call, intentionally not destroyed — destroying capture
    // participants pre-EndCapture invalidates the graph; bounded 2-call leak).
    cudaStream_t s2;
    cudaStreamCreateWithFlags(&s2, cudaStreamNonBlocking);
    cudaEvent_t evFork, evW, evXB, evClh, evS2;
    cudaEventCreateWithFlags(&evFork, cudaEventDisableTiming);
    cudaEventCreateWithFlags(&evW,    cudaEventDisableTiming);
    cudaEventCreateWithFlags(&evXB,   cudaEventDisableTiming);
    cudaEventCreateWithFlags(&evClh,  cudaEventDisableTiming);
    cudaEventCreateWithFlags(&evS2,   cudaEventDisableTiming);

    cudaEventRecord(evFork, 0);
    cudaStreamWaitEvent(s2, evFork, 0);

    const long long n4_top = (long long)M_TOP * IN_SIZE / 4;
    const long long n4_bot = (long long)M_BOT * IN_SIZE / 4;

    // ---- s2: wenc -> convert_x BOT -> clh -> wdec -> CSR ----
    convert_w_kernel<false><<<(EMBP * IN_SIZE + 255) / 256, 256, 0, s2>>>(
        wenc, wench, EMB, IN_SIZE, EMBP, IN_SIZE);
    cudaEventRecord(evW, s2);
    convert_x_kernel<<<(unsigned)((n4_bot + 255) / 256), 256, 0, s2>>>(
        (const float4*)x + n4_top, xh + (size_t)M_TOP * IN_SIZE, n4_bot);
    cudaEventRecord(evXB, s2);
    convert_w_kernel<true><<<(EMBP * EMBP + 255) / 256, 256, 0, s2>>>(
        conv_weight, clh, EMB, EMB, EMBP, EMBP);
    convert_w_kernel<false><<<(EMBP * EMBP + 255) / 256, 256, 0, s2>>>(
        lin_weight, clh + (size_t)EMBP * EMBP, EMB, EMB, EMBP, EMBP);
    cudaEventRecord(evClh, s2);
    convert_w_kernel<false><<<(IN_SIZE * EMBP + 255) / 256, 256, 0, s2>>>(
        wdec, wdech, IN_SIZE, EMB, IN_SIZE, EMBP);
    k_zero_cnt<<<(N_NODES + 1 + 255) / 256, 256, 0, s2>>>();
    k_count<<<(N_EDGES + 255) / 256, 256, 0, s2>>>(edge_index);
    k_scan<<<1, SCAN_T, 0, s2>>>();
    k_fill<<<(N_EDGES + 255) / 256, 256, 0, s2>>>(edge_index, edge_weight);
    cudaEventRecord(evS2, s2);   // covers wdec + CSR

    // ---- main: convert_x TOP -> GEMM1 TOP (overlaps s2's convert_x BOT) ----
    convert_x_kernel<<<(unsigned)((n4_top + 255) / 256), 256>>>(
        (const float4*)x, xh, n4_top);
    cudaStreamWaitEvent(0, evW, 0);
    {   // GEMM1 TOP
        dim3 grid(EMBP / 128, mtT);
        hgemm<2, true, true><<<grid, 256, DYNSMEM>>>(
            xh, IN_SIZE, wench, IN_SIZE, benc,
            nullptr, h, EMBP, M_TOP, EMB, IN_SIZE);
    }
    cudaStreamWaitEvent(0, evXB, 0);
    {   // GEMM1 BOT
        dim3 grid(EMBP / 128, mtB);
        hgemm<2, true, true><<<grid, 256, DYNSMEM>>>(
            xh + (size_t)M_TOP * IN_SIZE, IN_SIZE, wench, IN_SIZE, benc,
            nullptr, h + (size_t)M_TOP * EMBP, EMBP, M_BOT, EMB, IN_SIZE);
    }
    // 2) hw = h @ [conv^T ; lin]^T -> [h2 | agg_lin] fp16 (needs clh)
    cudaStreamWaitEvent(0, evClh, 0);
    {
        dim3 grid(CLW / 128, mt);
        hgemm<2, false, false><<<grid, 256, DYNSMEM>>>(
            h, EMBP, clh, EMBP, nullptr,
            nullptr, hw, CLW, N_NODES, CLW, EMBP);
    }
    // 3) gather (needs CSR + wdec done on s2) -> aggh fp16
    cudaStreamWaitEvent(0, evS2, 0);
    gather_nodes<<<N_NODES / 2, 128>>>(hw, aggh);
    // 4) out = aggh @ wdec^T + bdec (fp32)
    {
        dim3 grid(IN_SIZE / 128, mt);
        hgemm<0, true, false><<<grid, 256, DYNSMEM>>>(
            aggh, EMBP, wdech, EMBP, bdec,
            out, nullptr, IN_SIZE, N_NODES, IN_SIZE, EMBP);
    }
}

// round 17
// speedup vs baseline: 1.0289x; 1.0289x over previous
#include <cuda_runtime.h>
#include <cuda_fp16.h>
#include <cstdint>

#define N_NODES 50000
#define N_EDGES 800000
#define IN_SIZE 1024
#define EMB 500
#define EMBP 512
#define CLW 1024    // combined conv|lin output width

// ---------------------------------------------------------------------------
// Scratch (device globals: allocation-free per harness rules)
// ---------------------------------------------------------------------------
__device__ __half g_xh[(size_t)N_NODES * IN_SIZE];     // x -> fp16
__device__ __half g_h[(size_t)N_NODES * EMBP];         // sigmoid(enc) fp16
__device__ __half g_hw[(size_t)N_NODES * CLW];         // [h2 | agg_lin] fp16
__device__ __half g_aggh[(size_t)N_NODES * EMBP];      // final agg fp16
// fp16 weights, padded [NP][Kp], K contiguous
__device__ __half g_wench[EMBP * IN_SIZE];
__device__ __half g_clh[CLW * EMBP];                   // [conv^T ; lin] stacked
__device__ __half g_wdech[IN_SIZE * EMBP];
// CSR scratch
__device__ int   g_cnt[N_NODES + 1];
__device__ int   g_cur[N_NODES];
__device__ int   g_esrc[N_EDGES];
__device__ float g_ewt[N_EDGES];

// ---------------------------------------------------------------------------
// Convert kernels
// ---------------------------------------------------------------------------
__global__ __launch_bounds__(256) void convert_x_kernel(
    const float4* __restrict__ x, __half* __restrict__ xh, long long n4)
{
    long long i = (long long)blockIdx.x * blockDim.x + threadIdx.x;
    if (i >= n4) return;
    float4 v = x[i];
    __half2* p = reinterpret_cast<__half2*>(xh) + i * 2;
    p[0] = __floats2half2_rn(v.x, v.y);
    p[1] = __floats2half2_rn(v.z, v.w);
}

template <bool TRANS>
__global__ __launch_bounds__(256) void convert_w_kernel(
    const float* __restrict__ src, __half* __restrict__ dst,
    int N, int K, int NP, int Kp)
{
    int idx = blockIdx.x * blockDim.x + threadIdx.x;
    if (idx >= NP * Kp) return;
    int n = idx / Kp, k = idx - n * Kp;
    float v = 0.f;
    if (n < N && k < K)
        v = TRANS ? src[(long long)k * N + n] : src[(long long)n * K + k];
    dst[idx] = __float2half_rn(v);
}

// ---------------------------------------------------------------------------
// CSR build kernels
// ---------------------------------------------------------------------------
__global__ __launch_bounds__(256) void k_zero_cnt()
{
    int i = blockIdx.x * blockDim.x + threadIdx.x;
    if (i <= N_NODES) g_cnt[i] = 0;
}
__global__ __launch_bounds__(256) void k_count(const int* __restrict__ edge_index)
{
    int e = blockIdx.x * blockDim.x + threadIdx.x;
    if (e < N_EDGES) atomicAdd(&g_cnt[edge_index[N_EDGES + e]], 1);
}
#define SCAN_T 1024
#define SCAN_C 49   // 1024*49 = 50176 >= 50000
__global__ __launch_bounds__(SCAN_T) void k_scan()
{
    __shared__ int sh[SCAN_T];
    const int t = threadIdx.x;
    const int base = t * SCAN_C;
    int s = 0;
    #pragma unroll 4
    for (int j = 0; j < SCAN_C; j++) {
        int idx = base + j;
        if (idx < N_NODES) s += g_cnt[idx];
    }
    sh[t] = s;
    __syncthreads();
    for (int off = 1; off < SCAN_T; off <<= 1) {
        int v = (t >= off) ? sh[t - off] : 0;
        __syncthreads();
        sh[t] += v;
        __syncthreads();
    }
    int run = sh[t] - s;  // exclusive prefix
    for (int j = 0; j < SCAN_C; j++) {
        int idx = base + j;
        if (idx < N_NODES) {
            int c = g_cnt[idx];
            g_cnt[idx] = run;
            g_cur[idx] = run;
            run += c;
        }
    }
    if (t == 0) g_cnt[N_NODES] = N_EDGES;
}
__global__ __launch_bounds__(256) void k_fill(
    const int* __restrict__ edge_index, const float* __restrict__ ew)
{
    int e = blockIdx.x * blockDim.x + threadIdx.x;
    if (e >= N_EDGES) return;
    int dst = edge_index[N_EDGES + e];
    int pos = atomicAdd(&g_cur[dst], 1);
    g_esrc[pos] = edge_index[e];
    g_ewt[pos]  = ew[e];
}

// ---------------------------------------------------------------------------
// Gather (no atomics): acc = lin_part[n] + sum_e w_e * h2_part[src_e].
// hw row n = [h2 (512 fp16) | agg_lin (512 fp16)].
// 2 nodes per 128-thread block; each thread owns one 16B chunk (8 halves).
// ---------------------------------------------------------------------------
__global__ __launch_bounds__(128) void gather_nodes(
    const __half* __restrict__ hw, __half* __restrict__ aggh)
{
    const int n = blockIdx.x * 2 + (threadIdx.x >> 6);
    const int t = threadIdx.x & 63;        // 16B chunk within the 512-half row
    const int c = t * 8;                   // half index 0..504
    const int beg = g_cnt[n], end = g_cnt[n + 1];

    float acc[8];
    {   // base = lin part (cols 512..1023)
        uint4 bv = *reinterpret_cast<const uint4*>(hw + (long long)n * CLW + EMBP + c);
        const __half2* hb = reinterpret_cast<const __half2*>(&bv);
        #pragma unroll
        for (int j = 0; j < 4; j++) {
            float2 f = __half22float2(hb[j]);
            acc[j * 2] = f.x; acc[j * 2 + 1] = f.y;
        }
    }

    int e = beg;
    for (; e + 3 < end; e += 4) {
        int   s0 = g_esrc[e],   s1 = g_esrc[e+1], s2 = g_esrc[e+2], s3 = g_esrc[e+3];
        float w0 = g_ewt[e],    w1 = g_ewt[e+1],  w2 = g_ewt[e+2],  w3 = g_ewt[e+3];
        uint4 v0 = *reinterpret_cast<const uint4*>(hw + (long long)s0 * CLW + c);
        uint4 v1 = *reinterpret_cast<const uint4*>(hw + (long long)s1 * CLW + c);
        uint4 v2 = *reinterpret_cast<const uint4*>(hw + (long long)s2 * CLW + c);
        uint4 v3 = *reinterpret_cast<const uint4*>(hw + (long long)s3 * CLW + c);
        const __half2* h0 = reinterpret_cast<const __half2*>(&v0);
        const __half2* h1 = reinterpret_cast<const __half2*>(&v1);
        const __half2* h2 = reinterpret_cast<const __half2*>(&v2);
        const __half2* h3 = reinterpret_cast<const __half2*>(&v3);
        #pragma unroll
        for (int j = 0; j < 4; j++) {
            float2 f;
            f = __half22float2(h0[j]);
            acc[j*2] = fmaf(f.x, w0, acc[j*2]); acc[j*2+1] = fmaf(f.y, w0, acc[j*2+1]);
            f = __half22float2(h1[j]);
            acc[j*2] = fmaf(f.x, w1, acc[j*2]); acc[j*2+1] = fmaf(f.y, w1, acc[j*2+1]);
            f = __half22float2(h2[j]);
            acc[j*2] = fmaf(f.x, w2, acc[j*2]); acc[j*2+1] = fmaf(f.y, w2, acc[j*2+1]);
            f = __half22float2(h3[j]);
            acc[j*2] = fmaf(f.x, w3, acc[j*2]); acc[j*2+1] = fmaf(f.y, w3, acc[j*2+1]);
        }
    }
    for (; e < end; e++) {
        int   s0 = g_esrc[e];
        float w0 = g_ewt[e];
        uint4 v0 = *reinterpret_cast<const uint4*>(hw + (long long)s0 * CLW + c);
        const __half2* h0 = reinterpret_cast<const __half2*>(&v0);
        #pragma unroll
        for (int j = 0; j < 4; j++) {
            float2 f = __half22float2(h0[j]);
            acc[j*2] = fmaf(f.x, w0, acc[j*2]); acc[j*2+1] = fmaf(f.y, w0, acc[j*2+1]);
        }
    }

    uint4 ov;
    __half2* oh = reinterpret_cast<__half2*>(&ov);
    #pragma unroll
    for (int j = 0; j < 4; j++)
        oh[j] = __floats2half2_rn(acc[j * 2], acc[j * 2 + 1]);
    *reinterpret_cast<uint4*>(aggh + (long long)n * EMBP + c) = ov;
}

// ---------------------------------------------------------------------------
// Single-term fp16 GEMM, mma.sync m16n8k16 + cp.async 4-stage pipeline.
// C[M,N] = act(A[M,K] @ B[N,K]^T + bias). BM=BN=128, BK=32, 256 thr, 2 CTA/SM.
// smem rows padded to 40 halves (80B stride; conflict-free ldmatrix).
// OMODE: 0 = fp32 out, 2 = fp16 out. K mult of 32 (nk >= 16), B rows padded.
// ---------------------------------------------------------------------------
#define KPAD 40
#define TILE_BYTES (128 * KPAD * 2)        // 10240 per matrix
#define STAGE_BYTES (2 * TILE_BYTES)       // 20480
#define NSTAGE 4
#define DYNSMEM (NSTAGE * STAGE_BYTES)     // 81920 -> 2 CTAs/SM

__device__ __forceinline__ void ldsm4(uint32_t (&r)[4], uint32_t addr) {
    asm volatile("ldmatrix.sync.aligned.m8n8.x4.shared.b16 {%0,%1,%2,%3}, [%4];"
                 : "=r"(r[0]), "=r"(r[1]), "=r"(r[2]), "=r"(r[3]) : "r"(addr));
}
__device__ __forceinline__ void mma_f16(float (&c)[4], const uint32_t (&a)[4],
                                        uint32_t b0, uint32_t b1) {
    asm volatile(
        "mma.sync.aligned.m16n8k16.row.col.f32.f16.f16.f32 "
        "{%0,%1,%2,%3}, {%4,%5,%6,%7}, {%8,%9}, {%0,%1,%2,%3};"
        : "+f"(c[0]), "+f"(c[1]), "+f"(c[2]), "+f"(c[3])
        : "r"(a[0]), "r"(a[1]), "r"(a[2]), "r"(a[3]), "r"(b0), "r"(b1));
}
__device__ __forceinline__ void cpa16(uint32_t dst, const void* src, int sz) {
    asm volatile("cp.async.cg.shared.global [%0], [%1], 16, %2;"
                 :: "r"(dst), "l"(src), "r"(sz) : "memory");
}
__device__ __forceinline__ void cpa16u(uint32_t dst, const void* src) {
    asm volatile("cp.async.cg.shared.global [%0], [%1], 16;"
                 :: "r"(dst), "l"(src) : "memory");
}

template <int OMODE, bool BIAS, bool SIG>
__global__ __launch_bounds__(256, 2) void hgemm(
    const __half* __restrict__ A, int sA_,
    const __half* __restrict__ B, int sB_,
    const float* __restrict__ bias,
    float* __restrict__ C, __half* __restrict__ Ch, int sC,
    int M, int Nreal, int K)
{
    extern __shared__ char smem[];

    const int tid  = threadIdx.x;
    const int lane = tid & 31;
    const int warp = tid >> 5;
    const int wm = warp >> 1;   // 0..3
    const int wn = warp & 1;    // 0..1
    const int m0 = blockIdx.y * 128;
    const int n0 = blockIdx.x * 128;

    const int lrow = tid >> 1;
    const int cp0  = (tid & 1) * 2;
    const int gmA  = m0 + lrow;
    const int szA  = (gmA < M) ? 16 : 0;
    const __half* srcA = A + (long long)gmA * sA_ + cp0 * 8;
    const __half* srcB = B + (long long)(n0 + lrow) * sB_ + cp0 * 8;
    const uint32_t smem_u = (uint32_t)__cvta_generic_to_shared(smem);
    const uint32_t dRow = (uint32_t)(lrow * (KPAD * 2) + cp0 * 16);

    float acc[2][8][4];
    #pragma unroll
    for (int i = 0; i < 2; i++)
        #pragma unroll
        for (int j = 0; j < 8; j++)
            #pragma unroll
            for (int e = 0; e < 4; e++) acc[i][j][e] = 0.f;

    const int g = lane >> 3, r8 = lane & 7;
    const int nk = K / 32;

    auto load_stage = [&](int st, int k0) {
        const uint32_t aBase = smem_u + st * STAGE_BYTES + dRow;
        const uint32_t bBase = aBase + TILE_BYTES;
        cpa16(aBase,      srcA + k0, szA);
        cpa16(aBase + 16, srcA + k0 + 8, szA);
        cpa16u(bBase,      srcB + k0);
        cpa16u(bBase + 16, srcB + k0 + 8);
        asm volatile("cp.async.commit_group;" ::: "memory");
    };

    // prologue: 3 stages in flight (nk >= 16 always)
    load_stage(0, 0);
    load_stage(1, 32);
    load_stage(2, 64);

    const int aRowBase = wm * 32 + (g & 1) * 8 + r8;
    const int aColB    = (g >> 1) * 16;
    const int bRowBase = wn * 64 + (g >> 1) * 8 + r8;
    const int bColB    = (g & 1) * 16;

    for (int s = 0; s < nk; s++) {
        const int rem = nk - 1 - s;
        if (rem >= 2)      { asm volatile("cp.async.wait_group 2;" ::: "memory"); }
        else if (rem == 1) { asm volatile("cp.async.wait_group 1;" ::: "memory"); }
        else               { asm volatile("cp.async.wait_group 0;" ::: "memory"); }
        __syncthreads();   // stage s visible; all warps done with stage s-1 reads
        if (s + 3 < nk) load_stage((s + 3) % NSTAGE, (s + 3) * 32);

        const uint32_t aBuf = smem_u + (s % NSTAGE) * STAGE_BYTES;
        const uint32_t bBuf = aBuf + TILE_BYTES;

        #pragma unroll
        for (int ks = 0; ks < 2; ks++) {
            const int kkB = ks * 32;
            uint32_t a[2][4];
            #pragma unroll
            for (int mt = 0; mt < 2; mt++)
                ldsm4(a[mt], aBuf + (uint32_t)((aRowBase + mt * 16) * (KPAD * 2)
                                               + kkB + aColB));
            #pragma unroll
            for (int p = 0; p < 4; p++) {
                uint32_t b[4];
                ldsm4(b, bBuf + (uint32_t)((bRowBase + p * 16) * (KPAD * 2)
                                           + kkB + bColB));
                #pragma unroll
                for (int sx = 0; sx < 2; sx++)
                    #pragma unroll
                    for (int mt = 0; mt < 2; mt++)
                        mma_f16(acc[mt][p * 2 + sx], a[mt],
                                b[sx * 2], b[sx * 2 + 1]);
            }
        }
    }

    // ---- epilogue: packed stores (e-pairs are adjacent columns) ----
    const int rq = lane >> 2, cq = (lane & 3) * 2;
    #pragma unroll
    for (int mt = 0; mt < 2; mt++)
        #pragma unroll
        for (int nt = 0; nt < 8; nt++) {
            const int gc = n0 + wn * 64 + nt * 8 + cq;   // even
            #pragma unroll
            for (int half_ : {0, 1}) {
                const int gm = m0 + wm * 32 + mt * 16 + rq + half_ * 8;
                if (gm >= M) continue;
                float v0 = acc[mt][nt][half_ * 2 + 0];
                float v1 = acc[mt][nt][half_ * 2 + 1];
                if (BIAS || SIG) {
                    if (gc < Nreal)     { if (BIAS) v0 += bias[gc]; }
                    else v0 = 0.f;
                    if (gc + 1 < Nreal) { if (BIAS) v1 += bias[gc + 1]; }
                    else v1 = 0.f;
                    if (SIG) {
                        if (gc < Nreal)     v0 = 1.f / (1.f + expf(-v0));
                        if (gc + 1 < Nreal) v1 = 1.f / (1.f + expf(-v1));
                    }
                }
                if (OMODE == 2) {
                    *reinterpret_cast<__half2*>(Ch + (long long)gm * sC + gc)
                        = __floats2half2_rn(v0, v1);
                } else {
                    *reinterpret_cast<float2*>(C + (long long)gm * sC + gc)
                        = make_float2(v0, v1);
                }
            }
        }
}

// ---------------------------------------------------------------------------
extern "C" void kernel_launch(void* const* d_in, const int* in_sizes, int n_in,
                              void* d_out, int out_size)
{
    const float* x           = (const float*)d_in[0];
    const int*   edge_index  = (const int*)  d_in[1];
    const float* edge_weight = (const float*)d_in[2];
    const float* wenc        = (const float*)d_in[3];  // [EMB, IN_SIZE]
    const float* benc        = (const float*)d_in[4];
    const float* wdec        = (const float*)d_in[5];  // [IN_SIZE, EMB]
    const float* bdec        = (const float*)d_in[6];
    const float* conv_weight = (const float*)d_in[7];  // [EMB, EMB] (k, n)
    const float* lin_weight  = (const float*)d_in[8];  // [EMB, EMB] (n, k)
    float* out = (float*)d_out;

    __half *xh, *h, *hw, *aggh, *wench, *clh, *wdech;
    cudaGetSymbolAddress((void**)&xh, g_xh);
    cudaGetSymbolAddress((void**)&h, g_h);
    cudaGetSymbolAddress((void**)&hw, g_hw);
    cudaGetSymbolAddress((void**)&aggh, g_aggh);
    cudaGetSymbolAddress((void**)&wench, g_wench);
    cudaGetSymbolAddress((void**)&clh, g_clh);
    cudaGetSymbolAddress((void**)&wdech, g_wdech);

    cudaFuncSetAttribute(hgemm<2, true,  true >, cudaFuncAttributeMaxDynamicSharedMemorySize, DYNSMEM);
    cudaFuncSetAttribute(hgemm<2, false, false>, cudaFuncAttributeMaxDynamicSharedMemorySize, DYNSMEM);
    cudaFuncSetAttribute(hgemm<0, true,  false>, cudaFuncAttributeMaxDynamicSharedMemorySize, DYNSMEM);

    const int mt = (N_NODES + 127) / 128;    // 391

    // ---- ONE side stream + 4 events (smaller graph than R16, which passed
    // teardown). Created per call, intentionally not destroyed — destroying
    // capture participants pre-EndCapture invalidates the graph; bounded
    // 2-call leak, no device memory involved.
    cudaStream_t s2;
    cudaStreamCreateWithFlags(&s2, cudaStreamNonBlocking);
    cudaEvent_t evFork, evW, evClh, evS2;
    cudaEventCreateWithFlags(&evFork, cudaEventDisableTiming);
    cudaEventCreateWithFlags(&evW,    cudaEventDisableTiming);
    cudaEventCreateWithFlags(&evClh,  cudaEventDisableTiming);
    cudaEventCreateWithFlags(&evS2,   cudaEventDisableTiming);

    cudaEventRecord(evFork, 0);
    cudaStreamWaitEvent(s2, evFork, 0);

    // Kernel enqueue order fixes ncu launch indices:
    //   #0 convert_x, #1 wenc(s2), #2 GEMM1, #3 #4 clh(s2), #5 GEMM2 <- ncu -s 5
    //   #6 wdec(s2), #7..#10 CSR(s2), #11 gather, #12 decoder

    // #0: convert_x (full) on main
    {
        long long n4 = (long long)N_NODES * IN_SIZE / 4;
        convert_x_kernel<<<(unsigned)((n4 + 255) / 256), 256>>>((const float4*)x, xh, n4);
    }
    // #1: wenc on s2 (runs concurrently with convert_x)
    convert_w_kernel<false><<<(EMBP * IN_SIZE + 255) / 256, 256, 0, s2>>>(
        wenc, wench, EMB, IN_SIZE, EMBP, IN_SIZE);
    cudaEventRecord(evW, s2);

    // #2: GEMM1 (single launch — no TOP/BOT wave boundary)
    cudaStreamWaitEvent(0, evW, 0);
    {
        dim3 grid(EMBP / 128, mt);
        hgemm<2, true, true><<<grid, 256, DYNSMEM>>>(
            xh, IN_SIZE, wench, IN_SIZE, benc,
            nullptr, h, EMBP, N_NODES, EMB, IN_SIZE);
    }

    // #3, #4: clh converts on s2 (hidden under GEMM1)
    convert_w_kernel<true><<<(EMBP * EMBP + 255) / 256, 256, 0, s2>>>(
        conv_weight, clh, EMB, EMB, EMBP, EMBP);
    convert_w_kernel<false><<<(EMBP * EMBP + 255) / 256, 256, 0, s2>>>(
        lin_weight, clh + (size_t)EMBP * EMBP, EMB, EMB, EMBP, EMBP);
    cudaEventRecord(evClh, s2);

    // #5: GEMM2 -> [h2 | agg_lin]  (ncu -s 5 target)
    cudaStreamWaitEvent(0, evClh, 0);
    {
        dim3 grid(CLW / 128, mt);
        hgemm<2, false, false><<<grid, 256, DYNSMEM>>>(
            h, EMBP, clh, EMBP, nullptr,
            nullptr, hw, CLW, N_NODES, CLW, EMBP);
    }

    // #6..#10: wdec + CSR build on s2 (hidden under GEMM1/GEMM2)
    convert_w_kernel<false><<<(IN_SIZE * EMBP + 255) / 256, 256, 0, s2>>>(
        wdec, wdech, IN_SIZE, EMB, IN_SIZE, EMBP);
    k_zero_cnt<<<(N_NODES + 1 + 255) / 256, 256, 0, s2>>>();
    k_count<<<(N_EDGES + 255) / 256, 256, 0, s2>>>(edge_index);
    k_scan<<<1, SCAN_T, 0, s2>>>();
    k_fill<<<(N_EDGES + 255) / 256, 256, 0, s2>>>(edge_index, edge_weight);
    cudaEventRecord(evS2, s2);   // covers wdec + CSR

    // #11: gather (needs GEMM2 [stream order] + CSR/wdec [evS2])
    cudaStreamWaitEvent(0, evS2, 0);
    gather_nodes<<<N_NODES / 2, 128>>>(hw, aggh);

    // #12: decoder
    {
        dim3 grid(IN_SIZE / 128, mt);
        hgemm<0, true, false><<<grid, 256, DYNSMEM>>>(
            aggh, EMBP, wdech, EMBP, bdec,
            out, nullptr, IN_SIZE, N_NODES, IN_SIZE, EMBP);
    }
}